// round 16
// baseline (speedup 1.0000x reference)
#include <cuda_runtime.h>
#include <cuda_fp16.h>
#include <math.h>
#include <stdint.h>

#define N_NODES 50000
#define N_PAD   50048
#define E_EDGES 800000
#define ET (E_EDGES + N_NODES)   // with self loops
#define F_IN 256
#define C1 256                   // HEADS*HID
#define HEADS 4
#define HID 64
#define CLS 8
#define NEG 0.2f
#define NPART ((N_NODES + 1023) / 1024)   // 49

// ------------------- scratch (device globals; no allocation) -------------------
__device__ __half g_h1[(size_t)N_PAD * C1];      // x @ W1 (fp16 storage, fp32 math)
__device__ float g_h2[(size_t)N_NODES * CLS];    // (agg1 out) @ W2
__device__ float4 g_w1a[F_IN];                   // W1 @ a1s  (per k, 4 heads)
__device__ float4 g_w1d[F_IN];                   // W1 @ a1d
__device__ float g_as1[N_NODES * HEADS];
__device__ float g_ad1[N_NODES * HEADS];
__device__ float g_as2[N_NODES];
__device__ float g_ad2[N_NODES];
__device__ float4 g_ee[ET];                      // per-edge staging; reused by layer2
__device__ int   g_deg[N_NODES];
__device__ int   g_cnt[N_NODES];
__device__ int   g_rowptr[N_NODES + 1];
__device__ int   g_part[NPART];
__device__ int   g_csrc[ET];

__device__ __forceinline__ float lrelu(float x) { return x > 0.f ? x : NEG * x; }

__device__ __forceinline__ unsigned long long dup_f32(float v) {
    unsigned long long r;
    unsigned int u = __float_as_uint(v);
    asm("mov.b64 %0, {%1, %1};" : "=l"(r) : "r"(u));
    return r;
}

__device__ __forceinline__ float4 h4_to_f4(uint2 u) {
    __half2 a = *(__half2*)&u.x;
    __half2 b = *(__half2*)&u.y;
    float2 fa = __half22float2(a);
    float2 fb = __half22float2(b);
    return make_float4(fa.x, fa.y, fb.x, fb.y);
}

__device__ __forceinline__ uint32_t smem_u32(const void* p) {
    uint32_t a;
    asm("{ .reg .u64 t; cvta.to.shared.u64 t, %1; cvt.u32.u64 %0, t; }" : "=r"(a) : "l"(p));
    return a;
}

// ------------------- CSR build -------------------
__global__ void zero_counts_kernel() {
    int i = blockIdx.x * blockDim.x + threadIdx.x;
    if (i < N_NODES) { g_deg[i] = 0; g_cnt[i] = 0; }
}

__global__ void hist_kernel(const int* __restrict__ ei) {
    int e = blockIdx.x * blockDim.x + threadIdx.x;
    if (e >= ET) return;
    int dst = (e < E_EDGES) ? ei[E_EDGES + e] : (e - E_EDGES);
    atomicAdd(&g_deg[dst], 1);
}

__global__ void scan_a_kernel() {
    __shared__ int warpsums[32];
    int t = threadIdx.x;
    int idx = blockIdx.x * 1024 + t;
    int v = (idx < N_NODES) ? g_deg[idx] : 0;
    int x = v;
    #pragma unroll
    for (int o = 1; o < 32; o <<= 1) {
        int y = __shfl_up_sync(0xffffffffu, x, o);
        if ((t & 31) >= o) x += y;
    }
    if ((t & 31) == 31) warpsums[t >> 5] = x;
    __syncthreads();
    if (t < 32) {
        int y = warpsums[t];
        #pragma unroll
        for (int o = 1; o < 32; o <<= 1) {
            int z = __shfl_up_sync(0xffffffffu, y, o);
            if (t >= o) y += z;
        }
        warpsums[t] = y;
    }
    __syncthreads();
    int incl = x + ((t >= 32) ? warpsums[(t >> 5) - 1] : 0);
    if (idx < N_NODES) g_rowptr[idx] = incl - v;
    if (t == 1023) g_part[blockIdx.x] = incl;
}

__global__ void scan_b_kernel() {
    if (threadIdx.x == 0) {
        int run = 0;
        for (int b = 0; b < NPART; b++) {
            int v = g_part[b];
            g_part[b] = run;
            run += v;
        }
        g_rowptr[N_NODES] = run;
    }
}

__global__ void scan_c_kernel() {
    int idx = blockIdx.x * 1024 + threadIdx.x;
    if (idx < N_NODES) g_rowptr[idx] += g_part[blockIdx.x];
}

__global__ void scatter_kernel(const int* __restrict__ ei) {
    int e = blockIdx.x * blockDim.x + threadIdx.x;
    if (e >= ET) return;
    int src, dst;
    if (e < E_EDGES) { src = ei[e]; dst = ei[E_EDGES + e]; }
    else             { src = e - E_EDGES; dst = src; }
    int pos = g_rowptr[dst] + atomicAdd(&g_cnt[dst], 1);
    g_csrc[pos] = src;
}

// ------------------- w1a/w1d = W1 @ a1{s,d}: warp per k-row -------------------
__global__ void walpha_kernel(const float* __restrict__ W1,
                              const float* __restrict__ a1s,
                              const float* __restrict__ a1d) {
    int k = (blockIdx.x * blockDim.x + threadIdx.x) >> 5;
    int lane = threadIdx.x & 31;
    if (k >= F_IN) return;
    const float* wrow = W1 + (size_t)k * C1;
    float s[HEADS] = {0.f, 0.f, 0.f, 0.f};
    float d[HEADS] = {0.f, 0.f, 0.f, 0.f};
    #pragma unroll
    for (int i = 0; i < 8; i++) {
        int col = lane + 32 * i;
        int h = i >> 1;
        float v = wrow[col];
        s[h] += v * __ldg(&a1s[h * HID + (col & 63)]);
        d[h] += v * __ldg(&a1d[h * HID + (col & 63)]);
    }
    #pragma unroll
    for (int h = 0; h < HEADS; h++) {
        #pragma unroll
        for (int o = 16; o > 0; o >>= 1) {
            s[h] += __shfl_xor_sync(0xffffffffu, s[h], o);
            d[h] += __shfl_xor_sync(0xffffffffu, d[h], o);
        }
    }
    if (lane == 0) {
        g_w1a[k] = make_float4(s[0], s[1], s[2], s[3]);
        g_w1d[k] = make_float4(d[0], d[1], d[2], d[3]);
    }
}

// ------------------- as1/ad1 = x @ w1a/w1d: warp per node -------------------
__global__ void alpha_direct_kernel(const float* __restrict__ X) {
    int n = (blockIdx.x * blockDim.x + threadIdx.x) >> 5;
    int lane = threadIdx.x & 31;
    if (n >= N_NODES) return;
    const float* xrow = X + (size_t)n * F_IN;
    float4 sa = make_float4(0.f, 0.f, 0.f, 0.f);
    float4 da = make_float4(0.f, 0.f, 0.f, 0.f);
    #pragma unroll
    for (int i = 0; i < 8; i++) {
        int k = lane + 32 * i;
        float v = xrow[k];
        float4 wa = g_w1a[k];
        float4 wd = g_w1d[k];
        sa.x += v * wa.x; sa.y += v * wa.y; sa.z += v * wa.z; sa.w += v * wa.w;
        da.x += v * wd.x; da.y += v * wd.y; da.z += v * wd.z; da.w += v * wd.w;
    }
    #pragma unroll
    for (int o = 16; o > 0; o >>= 1) {
        sa.x += __shfl_xor_sync(0xffffffffu, sa.x, o);
        sa.y += __shfl_xor_sync(0xffffffffu, sa.y, o);
        sa.z += __shfl_xor_sync(0xffffffffu, sa.z, o);
        sa.w += __shfl_xor_sync(0xffffffffu, sa.w, o);
        da.x += __shfl_xor_sync(0xffffffffu, da.x, o);
        da.y += __shfl_xor_sync(0xffffffffu, da.y, o);
        da.z += __shfl_xor_sync(0xffffffffu, da.z, o);
        da.w += __shfl_xor_sync(0xffffffffu, da.w, o);
    }
    if (lane == 0) {
        *(float4*)&g_as1[n * HEADS] = sa;
        *(float4*)&g_ad1[n * HEADS] = da;
    }
}

// ------------------- GEMM1: cp.async double-buffered, fma.rn.f32x2, fp16 out --------
#define BM 128
#define BN 128
#define BK 32
#define SMEM_GEMM 65536

__global__ __launch_bounds__(256, 2) void gemm1_kernel(const float* __restrict__ X,
                                                        const float* __restrict__ W) {
    extern __shared__ float smem[];
    float* Asf = smem;                 // 8192 floats: [stage][m][k] 16B-chunk swizzled
    float* Bsf = smem + 8192;          // 8192 floats: [stage][k][n]
    uint32_t sA = smem_u32(smem);
    uint32_t sB = sA + 8192 * 4;

    int bm = blockIdx.x * BM;
    int bn = blockIdx.y * BN;
    int tid = threadIdx.x;
    int tx = tid & 15;
    int ty = tid >> 4;
    int sw = ty & 7;

    unsigned long long acc[8][4];
    #pragma unroll
    for (int i = 0; i < 8; i++)
        #pragma unroll
        for (int j = 0; j < 4; j++) acc[i][j] = 0ULL;

    #define LOAD_STAGE(stage, k0) do {                                               \
        _Pragma("unroll")                                                            \
        for (int it = 0; it < 4; it++) {                                             \
            int idx = tid + it * 256;                                                \
            int m = idx >> 3, c = idx & 7;                                           \
            int cs = c ^ ((m >> 3) & 7);                                             \
            uint32_t dst = sA + (stage) * 16384 + m * 128 + cs * 16;                 \
            const float* srcp = &X[(size_t)(bm + m) * F_IN + (k0) + c * 4];          \
            int sz = ((bm + m) < N_NODES) ? 16 : 0;                                  \
            asm volatile("cp.async.cg.shared.global [%0], [%1], 16, %2;"             \
                         :: "r"(dst), "l"(srcp), "r"(sz));                           \
        }                                                                            \
        _Pragma("unroll")                                                            \
        for (int it = 0; it < 4; it++) {                                             \
            int idx = tid + it * 256;                                                \
            int k = idx >> 5, c = idx & 31;                                          \
            uint32_t dst = sB + (stage) * 16384 + k * 512 + c * 16;                  \
            const float* srcp = &W[(size_t)((k0) + k) * C1 + bn + c * 4];            \
            asm volatile("cp.async.cg.shared.global [%0], [%1], 16;"                 \
                         :: "r"(dst), "l"(srcp));                                    \
        }                                                                            \
        asm volatile("cp.async.commit_group;");                                     \
    } while (0)

    LOAD_STAGE(0, 0);

    for (int cidx = 0; cidx < F_IN / BK; cidx++) {
        int cur = cidx & 1;
        if (cidx + 1 < F_IN / BK) {
            LOAD_STAGE((cidx + 1) & 1, (cidx + 1) * BK);
            asm volatile("cp.async.wait_group 1;");
        } else {
            asm volatile("cp.async.wait_group 0;");
        }
        __syncthreads();

        const float* astage = Asf + cur * 4096;
        const unsigned long long* bstage = (const unsigned long long*)(Bsf + cur * 4096);
        // 8 groups of 4 k; per group: 8x LDS.128 on A (4 k-values each), then 4 k-steps
        #pragma unroll
        for (int kq = 0; kq < 8; kq++) {
            int cw = (kq ^ sw) * 4;                // swizzled word offset of this 16B chunk
            float4 a4[8];
            #pragma unroll
            for (int i = 0; i < 8; i++)
                a4[i] = *(const float4*)&astage[(ty * 8 + i) * 32 + cw];
            #pragma unroll
            for (int kk = 0; kk < 4; kk++) {
                int k = kq * 4 + kk;
                const unsigned long long* brow = bstage + k * 64;
                unsigned long long b[4];
                #pragma unroll
                for (int j = 0; j < 4; j++) b[j] = brow[tx + 16 * j];
                unsigned long long a[8];
                #pragma unroll
                for (int i = 0; i < 8; i++) {
                    float av = (kk == 0) ? a4[i].x : (kk == 1) ? a4[i].y
                              : (kk == 2) ? a4[i].z : a4[i].w;
                    a[i] = dup_f32(av);
                }
                #pragma unroll
                for (int i = 0; i < 8; i++)
                    #pragma unroll
                    for (int j = 0; j < 4; j++)
                        asm("fma.rn.f32x2 %0, %1, %2, %3;"
                            : "=l"(acc[i][j]) : "l"(a[i]), "l"(b[j]), "l"(acc[i][j]));
            }
        }
        __syncthreads();
    }

    #pragma unroll
    for (int i = 0; i < 8; i++) {
        int gm = bm + ty * 8 + i;
        __half* orow = &g_h1[(size_t)gm * C1 + bn];
        #pragma unroll
        for (int j = 0; j < 4; j++) {
            int p = tx + 16 * j;
            float2 f = *(float2*)&acc[i][j];
            *(__half2*)&orow[2 * p] = __float22half2_rn(f);
        }
    }
    #undef LOAD_STAGE
}

// ------------------- agg1: merged softmax (no max) + feature agg + fused GEMM2 -------
__global__ void agg1_kernel(const float* __restrict__ b1, const float* __restrict__ W2,
                            const float* __restrict__ a2s, const float* __restrict__ a2d) {
    int node = (blockIdx.x * blockDim.x + threadIdx.x) >> 5;
    int lane = threadIdx.x & 31;
    if (node >= N_NODES) return;
    int beg = g_rowptr[node], end = g_rowptr[node + 1];
    float4 ad = *(const float4*)&g_ad1[node * HEADS];

    float4 sm = make_float4(0.f, 0.f, 0.f, 0.f);
    for (int i = beg + lane; i < end; i += 32) {
        int s = g_csrc[i];
        float4 a = *(const float4*)&g_as1[s * HEADS];
        float4 ex;
        ex.x = __expf(lrelu(a.x + ad.x));
        ex.y = __expf(lrelu(a.y + ad.y));
        ex.z = __expf(lrelu(a.z + ad.z));
        ex.w = __expf(lrelu(a.w + ad.w));
        g_ee[i] = ex;
        sm.x += ex.x; sm.y += ex.y; sm.z += ex.z; sm.w += ex.w;
    }
    #pragma unroll
    for (int o = 16; o > 0; o >>= 1) {
        sm.x += __shfl_xor_sync(0xffffffffu, sm.x, o);
        sm.y += __shfl_xor_sync(0xffffffffu, sm.y, o);
        sm.z += __shfl_xor_sync(0xffffffffu, sm.z, o);
        sm.w += __shfl_xor_sync(0xffffffffu, sm.w, o);
    }
    float4 inv;
    inv.x = 1.f / sm.x; inv.y = 1.f / sm.y; inv.z = 1.f / sm.z; inv.w = 1.f / sm.w;

    // pass B: feature aggregation over fp16 h1 rows, unrolled x8
    float4 acc0 = make_float4(0.f, 0.f, 0.f, 0.f);
    float4 acc1 = make_float4(0.f, 0.f, 0.f, 0.f);
    bool lo = (lane < 16);
    int i = beg;
    for (; i + 7 < end; i += 8) {
        int sidx[8];
        float4 exs[8];
        #pragma unroll
        for (int j = 0; j < 8; j++) {
            sidx[j] = g_csrc[i + j];
            exs[j] = __ldg(&g_ee[i + j]);
        }
        #pragma unroll
        for (int j = 0; j < 8; j++) {
            const uint2* hrow = (const uint2*)(g_h1 + (size_t)sidx[j] * C1);
            uint2 u0 = hrow[lane], u1 = hrow[32 + lane];
            float4 v0 = h4_to_f4(u0), v1 = h4_to_f4(u1);
            float a0 = (lo ? exs[j].x * inv.x : exs[j].y * inv.y);
            float a1 = (lo ? exs[j].z * inv.z : exs[j].w * inv.w);
            acc0.x += a0 * v0.x; acc0.y += a0 * v0.y; acc0.z += a0 * v0.z; acc0.w += a0 * v0.w;
            acc1.x += a1 * v1.x; acc1.y += a1 * v1.y; acc1.z += a1 * v1.z; acc1.w += a1 * v1.w;
        }
    }
    for (; i < end; i++) {
        int s = g_csrc[i];
        float4 ex = __ldg(&g_ee[i]);
        const uint2* hrow = (const uint2*)(g_h1 + (size_t)s * C1);
        float4 v0 = h4_to_f4(hrow[lane]);
        float4 v1 = h4_to_f4(hrow[32 + lane]);
        float a0 = (lo ? ex.x * inv.x : ex.y * inv.y);
        float a1 = (lo ? ex.z * inv.z : ex.w * inv.w);
        acc0.x += a0 * v0.x; acc0.y += a0 * v0.y; acc0.z += a0 * v0.z; acc0.w += a0 * v0.w;
        acc1.x += a1 * v1.x; acc1.y += a1 * v1.y; acc1.z += a1 * v1.z; acc1.w += a1 * v1.w;
    }

    float4 bb0 = __ldg((const float4*)&b1[4 * lane]);
    float4 bb1 = __ldg((const float4*)&b1[128 + 4 * lane]);
    float of[8];
    of[0] = fmaxf(acc0.x + bb0.x, 0.f); of[1] = fmaxf(acc0.y + bb0.y, 0.f);
    of[2] = fmaxf(acc0.z + bb0.z, 0.f); of[3] = fmaxf(acc0.w + bb0.w, 0.f);
    of[4] = fmaxf(acc1.x + bb1.x, 0.f); of[5] = fmaxf(acc1.y + bb1.y, 0.f);
    of[6] = fmaxf(acc1.z + bb1.z, 0.f); of[7] = fmaxf(acc1.w + bb1.w, 0.f);

    float hacc[CLS] = {};
    const float4* w2v = (const float4*)W2;
    #pragma unroll
    for (int j = 0; j < 8; j++) {
        int k = (j < 4) ? (4 * lane + j) : (128 + 4 * lane + (j - 4));
        float v = of[j];
        float4 wa = __ldg(&w2v[2 * k]);
        float4 wb = __ldg(&w2v[2 * k + 1]);
        hacc[0] += v * wa.x; hacc[1] += v * wa.y; hacc[2] += v * wa.z; hacc[3] += v * wa.w;
        hacc[4] += v * wb.x; hacc[5] += v * wb.y; hacc[6] += v * wb.z; hacc[7] += v * wb.w;
    }
    #pragma unroll
    for (int c = 0; c < CLS; c++)
        #pragma unroll
        for (int o = 16; o > 0; o >>= 1)
            hacc[c] += __shfl_xor_sync(0xffffffffu, hacc[c], o);
    if (lane == 0) {
        float s2 = 0.f, d2 = 0.f;
        #pragma unroll
        for (int c = 0; c < CLS; c++) {
            s2 += hacc[c] * __ldg(&a2s[c]);
            d2 += hacc[c] * __ldg(&a2d[c]);
        }
        float4* h2row = (float4*)(g_h2 + (size_t)node * CLS);
        h2row[0] = make_float4(hacc[0], hacc[1], hacc[2], hacc[3]);
        h2row[1] = make_float4(hacc[4], hacc[5], hacc[6], hacc[7]);
        g_as2[node] = s2;
        g_ad2[node] = d2;
    }
}

// ------------------- layer 2 aggregation (no max) + bias + log_softmax -----------
__global__ void agg2_kernel(const float* __restrict__ b2, float* __restrict__ out) {
    int n = blockIdx.x * blockDim.x + threadIdx.x;
    if (n >= N_NODES) return;
    int beg = g_rowptr[n], end = g_rowptr[n + 1];
    float adv = g_ad2[n];
    float* ebuf = (float*)g_ee;

    float sm = 0.f;
    for (int i = beg; i < end; i++) {
        float ex = __expf(lrelu(g_as2[g_csrc[i]] + adv));
        ebuf[i] = ex;
        sm += ex;
    }
    float invs = 1.f / sm;
    float acc[CLS] = {};
    for (int i = beg; i < end; i++) {
        int s = g_csrc[i];
        float al = ebuf[i] * invs;
        const float4* hp = (const float4*)(g_h2 + (size_t)s * CLS);
        float4 v0 = hp[0], v1 = hp[1];
        acc[0] += al * v0.x; acc[1] += al * v0.y; acc[2] += al * v0.z; acc[3] += al * v0.w;
        acc[4] += al * v1.x; acc[5] += al * v1.y; acc[6] += al * v1.z; acc[7] += al * v1.w;
    }
    float o[CLS];
    float m2 = -1e30f;
    #pragma unroll
    for (int c = 0; c < CLS; c++) {
        o[c] = acc[c] + __ldg(&b2[c]);
        m2 = fmaxf(m2, o[c]);
    }
    float ls = 0.f;
    #pragma unroll
    for (int c = 0; c < CLS; c++) ls += expf(o[c] - m2);
    ls = logf(ls);
    #pragma unroll
    for (int c = 0; c < CLS; c++) out[(size_t)n * CLS + c] = o[c] - m2 - ls;
}

// ------------------- launcher -------------------
extern "C" void kernel_launch(void* const* d_in, const int* in_sizes, int n_in,
                              void* d_out, int out_size) {
    const float* x    = (const float*)d_in[0];
    const int*   ei   = (const int*)d_in[1];
    const float* W1   = (const float*)d_in[2];
    const float* a1s  = (const float*)d_in[3];
    const float* a1d  = (const float*)d_in[4];
    const float* b1   = (const float*)d_in[5];
    const float* W2   = (const float*)d_in[6];
    const float* a2s  = (const float*)d_in[7];
    const float* a2d  = (const float*)d_in[8];
    const float* b2   = (const float*)d_in[9];
    float* out = (float*)d_out;

    static cudaStream_t s_side = nullptr;
    static cudaEvent_t ev_fork = nullptr, ev_side = nullptr;
    if (s_side == nullptr) {
        cudaStreamCreateWithFlags(&s_side, cudaStreamNonBlocking);
        cudaEventCreateWithFlags(&ev_fork, cudaEventDisableTiming);
        cudaEventCreateWithFlags(&ev_side, cudaEventDisableTiming);
        cudaFuncSetAttribute(gemm1_kernel,
                             cudaFuncAttributeMaxDynamicSharedMemorySize, SMEM_GEMM);
    }

    // fork: CSR build + attention coefficient precompute on side stream
    cudaEventRecord(ev_fork, 0);
    cudaStreamWaitEvent(s_side, ev_fork, 0);

    zero_counts_kernel<<<(N_NODES + 255) / 256, 256, 0, s_side>>>();
    hist_kernel<<<(ET + 255) / 256, 256, 0, s_side>>>(ei);
    scan_a_kernel<<<NPART, 1024, 0, s_side>>>();
    scan_b_kernel<<<1, 32, 0, s_side>>>();
    scan_c_kernel<<<NPART, 1024, 0, s_side>>>();
    scatter_kernel<<<(ET + 255) / 256, 256, 0, s_side>>>(ei);
    walpha_kernel<<<(F_IN * 32 + 255) / 256, 256, 0, s_side>>>(W1, a1s, a1d);
    alpha_direct_kernel<<<(N_NODES * 32 + 255) / 256, 256, 0, s_side>>>(x);
    cudaEventRecord(ev_side, s_side);

    // main stream: dense GEMM1 (cp.async double-buffered)
    dim3 g1((N_NODES + BM - 1) / BM, C1 / BN);
    gemm1_kernel<<<g1, 256, SMEM_GEMM>>>(x, W1);

    // join, then edge-dependent work on main stream
    cudaStreamWaitEvent(0, ev_side, 0);
    agg1_kernel<<<(N_NODES * 32 + 255) / 256, 256>>>(b1, W2, a2s, a2d);
    agg2_kernel<<<(N_NODES + 255) / 256, 256>>>(b2, out);
}

// round 17
// speedup vs baseline: 1.6282x; 1.6282x over previous
#include <cuda_runtime.h>
#include <cuda_fp16.h>
#include <math.h>
#include <stdint.h>

#define N_NODES 50000
#define N_PAD   50048
#define E_EDGES 800000
#define ET (E_EDGES + N_NODES)   // with self loops
#define F_IN 256
#define C1 256                   // HEADS*HID
#define HEADS 4
#define HID 64
#define CLS 8
#define NEG 0.2f
#define NPART ((N_NODES + 1023) / 1024)   // 49

// ------------------- scratch (device globals; no allocation) -------------------
__device__ __half g_h1[(size_t)N_PAD * C1];      // x @ W1 (fp16 storage, fp32 math)
__device__ float g_h2[(size_t)N_NODES * CLS];    // (agg1 out) @ W2
__device__ float4 g_w1a[F_IN];                   // W1 @ a1s  (per k, 4 heads)
__device__ float4 g_w1d[F_IN];                   // W1 @ a1d
__device__ float g_as1[N_NODES * HEADS];
__device__ float g_ad1[N_NODES * HEADS];
__device__ float g_as2[N_NODES];
__device__ float g_ad2[N_NODES];
__device__ float4 g_ee[ET];                      // per-edge staging; reused by layer2
__device__ int   g_deg[N_NODES];
__device__ int   g_cnt[N_NODES];
__device__ int   g_rowptr[N_NODES + 1];
__device__ int   g_part[NPART];
__device__ int   g_csrc[ET];

__device__ __forceinline__ float lrelu(float x) { return x > 0.f ? x : NEG * x; }

__device__ __forceinline__ unsigned long long dup_f32(float v) {
    unsigned long long r;
    unsigned int u = __float_as_uint(v);
    asm("mov.b64 %0, {%1, %1};" : "=l"(r) : "r"(u));
    return r;
}

__device__ __forceinline__ float4 h4_to_f4(uint2 u) {
    __half2 a = *(__half2*)&u.x;
    __half2 b = *(__half2*)&u.y;
    float2 fa = __half22float2(a);
    float2 fb = __half22float2(b);
    return make_float4(fa.x, fa.y, fb.x, fb.y);
}

__device__ __forceinline__ uint32_t smem_u32(const void* p) {
    uint32_t a;
    asm("{ .reg .u64 t; cvta.to.shared.u64 t, %1; cvt.u32.u64 %0, t; }" : "=r"(a) : "l"(p));
    return a;
}

// ------------------- CSR build -------------------
__global__ void zero_counts_kernel() {
    int i = blockIdx.x * blockDim.x + threadIdx.x;
    if (i < N_NODES) { g_deg[i] = 0; g_cnt[i] = 0; }
}

__global__ void hist_kernel(const int* __restrict__ ei) {
    int e = blockIdx.x * blockDim.x + threadIdx.x;
    if (e >= ET) return;
    int dst = (e < E_EDGES) ? ei[E_EDGES + e] : (e - E_EDGES);
    atomicAdd(&g_deg[dst], 1);
}

__global__ void scan_a_kernel() {
    __shared__ int warpsums[32];
    int t = threadIdx.x;
    int idx = blockIdx.x * 1024 + t;
    int v = (idx < N_NODES) ? g_deg[idx] : 0;
    int x = v;
    #pragma unroll
    for (int o = 1; o < 32; o <<= 1) {
        int y = __shfl_up_sync(0xffffffffu, x, o);
        if ((t & 31) >= o) x += y;
    }
    if ((t & 31) == 31) warpsums[t >> 5] = x;
    __syncthreads();
    if (t < 32) {
        int y = warpsums[t];
        #pragma unroll
        for (int o = 1; o < 32; o <<= 1) {
            int z = __shfl_up_sync(0xffffffffu, y, o);
            if (t >= o) y += z;
        }
        warpsums[t] = y;
    }
    __syncthreads();
    int incl = x + ((t >= 32) ? warpsums[(t >> 5) - 1] : 0);
    if (idx < N_NODES) g_rowptr[idx] = incl - v;
    if (t == 1023) g_part[blockIdx.x] = incl;
}

__global__ void scan_b_kernel() {
    if (threadIdx.x == 0) {
        int run = 0;
        for (int b = 0; b < NPART; b++) {
            int v = g_part[b];
            g_part[b] = run;
            run += v;
        }
        g_rowptr[N_NODES] = run;
    }
}

__global__ void scan_c_kernel() {
    int idx = blockIdx.x * 1024 + threadIdx.x;
    if (idx < N_NODES) g_rowptr[idx] += g_part[blockIdx.x];
}

__global__ void scatter_kernel(const int* __restrict__ ei) {
    int e = blockIdx.x * blockDim.x + threadIdx.x;
    if (e >= ET) return;
    int src, dst;
    if (e < E_EDGES) { src = ei[e]; dst = ei[E_EDGES + e]; }
    else             { src = e - E_EDGES; dst = src; }
    int pos = g_rowptr[dst] + atomicAdd(&g_cnt[dst], 1);
    g_csrc[pos] = src;
}

// ------------------- w1a/w1d = W1 @ a1{s,d}: warp per k-row -------------------
__global__ void walpha_kernel(const float* __restrict__ W1,
                              const float* __restrict__ a1s,
                              const float* __restrict__ a1d) {
    int k = (blockIdx.x * blockDim.x + threadIdx.x) >> 5;
    int lane = threadIdx.x & 31;
    if (k >= F_IN) return;
    const float* wrow = W1 + (size_t)k * C1;
    float s[HEADS] = {0.f, 0.f, 0.f, 0.f};
    float d[HEADS] = {0.f, 0.f, 0.f, 0.f};
    #pragma unroll
    for (int i = 0; i < 8; i++) {
        int col = lane + 32 * i;
        int h = i >> 1;
        float v = wrow[col];
        s[h] += v * __ldg(&a1s[h * HID + (col & 63)]);
        d[h] += v * __ldg(&a1d[h * HID + (col & 63)]);
    }
    #pragma unroll
    for (int h = 0; h < HEADS; h++) {
        #pragma unroll
        for (int o = 16; o > 0; o >>= 1) {
            s[h] += __shfl_xor_sync(0xffffffffu, s[h], o);
            d[h] += __shfl_xor_sync(0xffffffffu, d[h], o);
        }
    }
    if (lane == 0) {
        g_w1a[k] = make_float4(s[0], s[1], s[2], s[3]);
        g_w1d[k] = make_float4(d[0], d[1], d[2], d[3]);
    }
}

// ------------------- as1/ad1 = x @ w1a/w1d: warp per node -------------------
__global__ void alpha_direct_kernel(const float* __restrict__ X) {
    int n = (blockIdx.x * blockDim.x + threadIdx.x) >> 5;
    int lane = threadIdx.x & 31;
    if (n >= N_NODES) return;
    const float* xrow = X + (size_t)n * F_IN;
    float4 sa = make_float4(0.f, 0.f, 0.f, 0.f);
    float4 da = make_float4(0.f, 0.f, 0.f, 0.f);
    #pragma unroll
    for (int i = 0; i < 8; i++) {
        int k = lane + 32 * i;
        float v = xrow[k];
        float4 wa = g_w1a[k];
        float4 wd = g_w1d[k];
        sa.x += v * wa.x; sa.y += v * wa.y; sa.z += v * wa.z; sa.w += v * wa.w;
        da.x += v * wd.x; da.y += v * wd.y; da.z += v * wd.z; da.w += v * wd.w;
    }
    #pragma unroll
    for (int o = 16; o > 0; o >>= 1) {
        sa.x += __shfl_xor_sync(0xffffffffu, sa.x, o);
        sa.y += __shfl_xor_sync(0xffffffffu, sa.y, o);
        sa.z += __shfl_xor_sync(0xffffffffu, sa.z, o);
        sa.w += __shfl_xor_sync(0xffffffffu, sa.w, o);
        da.x += __shfl_xor_sync(0xffffffffu, da.x, o);
        da.y += __shfl_xor_sync(0xffffffffu, da.y, o);
        da.z += __shfl_xor_sync(0xffffffffu, da.z, o);
        da.w += __shfl_xor_sync(0xffffffffu, da.w, o);
    }
    if (lane == 0) {
        *(float4*)&g_as1[n * HEADS] = sa;
        *(float4*)&g_ad1[n * HEADS] = da;
    }
}

// ------------------- GEMM1: cp.async double-buffered, fma.rn.f32x2, fp16 out --------
#define BM 128
#define BN 128
#define BK 32
#define SMEM_GEMM 65536

__global__ __launch_bounds__(256, 2) void gemm1_kernel(const float* __restrict__ X,
                                                        const float* __restrict__ W) {
    extern __shared__ float smem[];
    float* Asf = smem;                 // 8192 floats: [stage][m][k] 16B-chunk swizzled
    float* Bsf = smem + 8192;          // 8192 floats: [stage][k][n]
    uint32_t sA = smem_u32(smem);
    uint32_t sB = sA + 8192 * 4;

    int bm = blockIdx.x * BM;
    int bn = blockIdx.y * BN;
    int tid = threadIdx.x;
    int tx = tid & 15;
    int ty = tid >> 4;
    int sw = ty & 7;

    unsigned long long acc[8][4];
    #pragma unroll
    for (int i = 0; i < 8; i++)
        #pragma unroll
        for (int j = 0; j < 4; j++) acc[i][j] = 0ULL;

    #define LOAD_STAGE(stage, k0) do {                                               \
        _Pragma("unroll")                                                            \
        for (int it = 0; it < 4; it++) {                                             \
            int idx = tid + it * 256;                                                \
            int m = idx >> 3, c = idx & 7;                                           \
            int cs = c ^ ((m >> 3) & 7);                                             \
            uint32_t dst = sA + (stage) * 16384 + m * 128 + cs * 16;                 \
            const float* srcp = &X[(size_t)(bm + m) * F_IN + (k0) + c * 4];          \
            int sz = ((bm + m) < N_NODES) ? 16 : 0;                                  \
            asm volatile("cp.async.cg.shared.global [%0], [%1], 16, %2;"             \
                         :: "r"(dst), "l"(srcp), "r"(sz));                           \
        }                                                                            \
        _Pragma("unroll")                                                            \
        for (int it = 0; it < 4; it++) {                                             \
            int idx = tid + it * 256;                                                \
            int k = idx >> 5, c = idx & 31;                                          \
            uint32_t dst = sB + (stage) * 16384 + k * 512 + c * 16;                  \
            const float* srcp = &W[(size_t)((k0) + k) * C1 + bn + c * 4];            \
            asm volatile("cp.async.cg.shared.global [%0], [%1], 16;"                 \
                         :: "r"(dst), "l"(srcp));                                    \
        }                                                                            \
        asm volatile("cp.async.commit_group;");                                     \
    } while (0)

    LOAD_STAGE(0, 0);

    for (int cidx = 0; cidx < F_IN / BK; cidx++) {
        int cur = cidx & 1;
        if (cidx + 1 < F_IN / BK) {
            LOAD_STAGE((cidx + 1) & 1, (cidx + 1) * BK);
            asm volatile("cp.async.wait_group 1;");
        } else {
            asm volatile("cp.async.wait_group 0;");
        }
        __syncthreads();

        const float* arow = Asf + cur * 4096 + (ty * 8) * 32;   // word-indexed
        const unsigned long long* bstage = (const unsigned long long*)(Bsf + cur * 4096);
        #pragma unroll 4
        for (int k = 0; k < BK; k++) {
            int koff = (((k >> 2) ^ sw) << 2) + (k & 3);        // swizzled word offset
            unsigned long long a[8];
            #pragma unroll
            for (int i = 0; i < 8; i++)
                a[i] = dup_f32(arow[i * 32 + koff]);
            const unsigned long long* brow = bstage + k * 64;
            unsigned long long b[4];
            #pragma unroll
            for (int j = 0; j < 4; j++) b[j] = brow[tx + 16 * j];
            #pragma unroll
            for (int i = 0; i < 8; i++)
                #pragma unroll
                for (int j = 0; j < 4; j++)
                    asm("fma.rn.f32x2 %0, %1, %2, %3;"
                        : "=l"(acc[i][j]) : "l"(a[i]), "l"(b[j]), "l"(acc[i][j]));
        }
        __syncthreads();
    }

    #pragma unroll
    for (int i = 0; i < 8; i++) {
        int gm = bm + ty * 8 + i;
        __half* orow = &g_h1[(size_t)gm * C1 + bn];
        #pragma unroll
        for (int j = 0; j < 4; j++) {
            int p = tx + 16 * j;
            float2 f = *(float2*)&acc[i][j];
            *(__half2*)&orow[2 * p] = __float22half2_rn(f);
        }
    }
    #undef LOAD_STAGE
}

// ------------------- agg1: merged softmax (no max) + feature agg + fused GEMM2 -------
__global__ void agg1_kernel(const float* __restrict__ b1, const float* __restrict__ W2,
                            const float* __restrict__ a2s, const float* __restrict__ a2d) {
    int node = (blockIdx.x * blockDim.x + threadIdx.x) >> 5;
    int lane = threadIdx.x & 31;
    if (node >= N_NODES) return;
    int beg = g_rowptr[node], end = g_rowptr[node + 1];
    float4 ad = *(const float4*)&g_ad1[node * HEADS];

    float4 sm = make_float4(0.f, 0.f, 0.f, 0.f);
    for (int i = beg + lane; i < end; i += 32) {
        int s = g_csrc[i];
        float4 a = *(const float4*)&g_as1[s * HEADS];
        float4 ex;
        ex.x = __expf(lrelu(a.x + ad.x));
        ex.y = __expf(lrelu(a.y + ad.y));
        ex.z = __expf(lrelu(a.z + ad.z));
        ex.w = __expf(lrelu(a.w + ad.w));
        g_ee[i] = ex;
        sm.x += ex.x; sm.y += ex.y; sm.z += ex.z; sm.w += ex.w;
    }
    #pragma unroll
    for (int o = 16; o > 0; o >>= 1) {
        sm.x += __shfl_xor_sync(0xffffffffu, sm.x, o);
        sm.y += __shfl_xor_sync(0xffffffffu, sm.y, o);
        sm.z += __shfl_xor_sync(0xffffffffu, sm.z, o);
        sm.w += __shfl_xor_sync(0xffffffffu, sm.w, o);
    }
    float4 inv;
    inv.x = 1.f / sm.x; inv.y = 1.f / sm.y; inv.z = 1.f / sm.z; inv.w = 1.f / sm.w;

    float4 acc0 = make_float4(0.f, 0.f, 0.f, 0.f);
    float4 acc1 = make_float4(0.f, 0.f, 0.f, 0.f);
    bool lo = (lane < 16);
    int i = beg;
    for (; i + 3 < end; i += 4) {
        int s0 = g_csrc[i],     s1 = g_csrc[i + 1];
        int s2 = g_csrc[i + 2], s3 = g_csrc[i + 3];
        float4 ex0 = __ldg(&g_ee[i]);
        float4 ex1 = __ldg(&g_ee[i + 1]);
        float4 ex2 = __ldg(&g_ee[i + 2]);
        float4 ex3 = __ldg(&g_ee[i + 3]);
        const uint2* r0 = (const uint2*)(g_h1 + (size_t)s0 * C1);
        const uint2* r1 = (const uint2*)(g_h1 + (size_t)s1 * C1);
        const uint2* r2 = (const uint2*)(g_h1 + (size_t)s2 * C1);
        const uint2* r3 = (const uint2*)(g_h1 + (size_t)s3 * C1);
        uint2 u00 = r0[lane], u01 = r0[32 + lane];
        uint2 u10 = r1[lane], u11 = r1[32 + lane];
        uint2 u20 = r2[lane], u21 = r2[32 + lane];
        uint2 u30 = r3[lane], u31 = r3[32 + lane];
        float4 v00 = h4_to_f4(u00), v01 = h4_to_f4(u01);
        float4 v10 = h4_to_f4(u10), v11 = h4_to_f4(u11);
        float4 v20 = h4_to_f4(u20), v21 = h4_to_f4(u21);
        float4 v30 = h4_to_f4(u30), v31 = h4_to_f4(u31);
        float a00 = (lo ? ex0.x * inv.x : ex0.y * inv.y);
        float a01 = (lo ? ex0.z * inv.z : ex0.w * inv.w);
        float a10 = (lo ? ex1.x * inv.x : ex1.y * inv.y);
        float a11 = (lo ? ex1.z * inv.z : ex1.w * inv.w);
        float a20 = (lo ? ex2.x * inv.x : ex2.y * inv.y);
        float a21 = (lo ? ex2.z * inv.z : ex2.w * inv.w);
        float a30 = (lo ? ex3.x * inv.x : ex3.y * inv.y);
        float a31 = (lo ? ex3.z * inv.z : ex3.w * inv.w);
        acc0.x += a00 * v00.x; acc0.y += a00 * v00.y; acc0.z += a00 * v00.z; acc0.w += a00 * v00.w;
        acc1.x += a01 * v01.x; acc1.y += a01 * v01.y; acc1.z += a01 * v01.z; acc1.w += a01 * v01.w;
        acc0.x += a10 * v10.x; acc0.y += a10 * v10.y; acc0.z += a10 * v10.z; acc0.w += a10 * v10.w;
        acc1.x += a11 * v11.x; acc1.y += a11 * v11.y; acc1.z += a11 * v11.z; acc1.w += a11 * v11.w;
        acc0.x += a20 * v20.x; acc0.y += a20 * v20.y; acc0.z += a20 * v20.z; acc0.w += a20 * v20.w;
        acc1.x += a21 * v21.x; acc1.y += a21 * v21.y; acc1.z += a21 * v21.z; acc1.w += a21 * v21.w;
        acc0.x += a30 * v30.x; acc0.y += a30 * v30.y; acc0.z += a30 * v30.z; acc0.w += a30 * v30.w;
        acc1.x += a31 * v31.x; acc1.y += a31 * v31.y; acc1.z += a31 * v31.z; acc1.w += a31 * v31.w;
    }
    for (; i < end; i++) {
        int s = g_csrc[i];
        float4 ex = __ldg(&g_ee[i]);
        const uint2* hrow = (const uint2*)(g_h1 + (size_t)s * C1);
        float4 v0 = h4_to_f4(hrow[lane]);
        float4 v1 = h4_to_f4(hrow[32 + lane]);
        float a0 = (lo ? ex.x * inv.x : ex.y * inv.y);
        float a1 = (lo ? ex.z * inv.z : ex.w * inv.w);
        acc0.x += a0 * v0.x; acc0.y += a0 * v0.y; acc0.z += a0 * v0.z; acc0.w += a0 * v0.w;
        acc1.x += a1 * v1.x; acc1.y += a1 * v1.y; acc1.z += a1 * v1.z; acc1.w += a1 * v1.w;
    }

    float4 bb0 = __ldg((const float4*)&b1[4 * lane]);
    float4 bb1 = __ldg((const float4*)&b1[128 + 4 * lane]);
    float of[8];
    of[0] = fmaxf(acc0.x + bb0.x, 0.f); of[1] = fmaxf(acc0.y + bb0.y, 0.f);
    of[2] = fmaxf(acc0.z + bb0.z, 0.f); of[3] = fmaxf(acc0.w + bb0.w, 0.f);
    of[4] = fmaxf(acc1.x + bb1.x, 0.f); of[5] = fmaxf(acc1.y + bb1.y, 0.f);
    of[6] = fmaxf(acc1.z + bb1.z, 0.f); of[7] = fmaxf(acc1.w + bb1.w, 0.f);

    float hacc[CLS] = {};
    const float4* w2v = (const float4*)W2;
    #pragma unroll
    for (int j = 0; j < 8; j++) {
        int k = (j < 4) ? (4 * lane + j) : (128 + 4 * lane + (j - 4));
        float v = of[j];
        float4 wa = __ldg(&w2v[2 * k]);
        float4 wb = __ldg(&w2v[2 * k + 1]);
        hacc[0] += v * wa.x; hacc[1] += v * wa.y; hacc[2] += v * wa.z; hacc[3] += v * wa.w;
        hacc[4] += v * wb.x; hacc[5] += v * wb.y; hacc[6] += v * wb.z; hacc[7] += v * wb.w;
    }
    #pragma unroll
    for (int c = 0; c < CLS; c++)
        #pragma unroll
        for (int o = 16; o > 0; o >>= 1)
            hacc[c] += __shfl_xor_sync(0xffffffffu, hacc[c], o);
    if (lane == 0) {
        float s2 = 0.f, d2 = 0.f;
        #pragma unroll
        for (int c = 0; c < CLS; c++) {
            s2 += hacc[c] * __ldg(&a2s[c]);
            d2 += hacc[c] * __ldg(&a2d[c]);
        }
        float4* h2row = (float4*)(g_h2 + (size_t)node * CLS);
        h2row[0] = make_float4(hacc[0], hacc[1], hacc[2], hacc[3]);
        h2row[1] = make_float4(hacc[4], hacc[5], hacc[6], hacc[7]);
        g_as2[node] = s2;
        g_ad2[node] = d2;
    }
}

// ------------------- layer 2 aggregation (no max) + bias + log_softmax -----------
__global__ void agg2_kernel(const float* __restrict__ b2, float* __restrict__ out) {
    int n = blockIdx.x * blockDim.x + threadIdx.x;
    if (n >= N_NODES) return;
    int beg = g_rowptr[n], end = g_rowptr[n + 1];
    float adv = g_ad2[n];
    float* ebuf = (float*)g_ee;

    // pass 1: gather + exp, unrolled x4 (scalar, low register pressure)
    float sm = 0.f;
    int i = beg;
    for (; i + 3 < end; i += 4) {
        int s0 = g_csrc[i],     s1 = g_csrc[i + 1];
        int s2 = g_csrc[i + 2], s3 = g_csrc[i + 3];
        float t0 = g_as2[s0], t1 = g_as2[s1];
        float t2 = g_as2[s2], t3 = g_as2[s3];
        float e0 = __expf(lrelu(t0 + adv));
        float e1 = __expf(lrelu(t1 + adv));
        float e2 = __expf(lrelu(t2 + adv));
        float e3 = __expf(lrelu(t3 + adv));
        ebuf[i] = e0; ebuf[i + 1] = e1; ebuf[i + 2] = e2; ebuf[i + 3] = e3;
        sm += e0 + e1 + e2 + e3;
    }
    for (; i < end; i++) {
        float ex = __expf(lrelu(g_as2[g_csrc[i]] + adv));
        ebuf[i] = ex;
        sm += ex;
    }
    float invs = 1.f / sm;
    float acc[CLS] = {};
    for (i = beg; i < end; i++) {
        int s = g_csrc[i];
        float al = ebuf[i] * invs;
        const float4* hp = (const float4*)(g_h2 + (size_t)s * CLS);
        float4 v0 = hp[0], v1 = hp[1];
        acc[0] += al * v0.x; acc[1] += al * v0.y; acc[2] += al * v0.z; acc[3] += al * v0.w;
        acc[4] += al * v1.x; acc[5] += al * v1.y; acc[6] += al * v1.z; acc[7] += al * v1.w;
    }
    float o[CLS];
    float m2 = -1e30f;
    #pragma unroll
    for (int c = 0; c < CLS; c++) {
        o[c] = acc[c] + __ldg(&b2[c]);
        m2 = fmaxf(m2, o[c]);
    }
    float ls = 0.f;
    #pragma unroll
    for (int c = 0; c < CLS; c++) ls += expf(o[c] - m2);
    ls = logf(ls);
    #pragma unroll
    for (int c = 0; c < CLS; c++) out[(size_t)n * CLS + c] = o[c] - m2 - ls;
}

// ------------------- launcher -------------------
extern "C" void kernel_launch(void* const* d_in, const int* in_sizes, int n_in,
                              void* d_out, int out_size) {
    const float* x    = (const float*)d_in[0];
    const int*   ei   = (const int*)d_in[1];
    const float* W1   = (const float*)d_in[2];
    const float* a1s  = (const float*)d_in[3];
    const float* a1d  = (const float*)d_in[4];
    const float* b1   = (const float*)d_in[5];
    const float* W2   = (const float*)d_in[6];
    const float* a2s  = (const float*)d_in[7];
    const float* a2d  = (const float*)d_in[8];
    const float* b2   = (const float*)d_in[9];
    float* out = (float*)d_out;

    static cudaStream_t s_side = nullptr;
    static cudaEvent_t ev_fork = nullptr, ev_side = nullptr;
    if (s_side == nullptr) {
        cudaStreamCreateWithFlags(&s_side, cudaStreamNonBlocking);
        cudaEventCreateWithFlags(&ev_fork, cudaEventDisableTiming);
        cudaEventCreateWithFlags(&ev_side, cudaEventDisableTiming);
        cudaFuncSetAttribute(gemm1_kernel,
                             cudaFuncAttributeMaxDynamicSharedMemorySize, SMEM_GEMM);
    }

    // fork: CSR build + attention coefficient precompute on side stream
    cudaEventRecord(ev_fork, 0);
    cudaStreamWaitEvent(s_side, ev_fork, 0);

    zero_counts_kernel<<<(N_NODES + 255) / 256, 256, 0, s_side>>>();
    hist_kernel<<<(ET + 255) / 256, 256, 0, s_side>>>(ei);
    scan_a_kernel<<<NPART, 1024, 0, s_side>>>();
    scan_b_kernel<<<1, 32, 0, s_side>>>();
    scan_c_kernel<<<NPART, 1024, 0, s_side>>>();
    scatter_kernel<<<(ET + 255) / 256, 256, 0, s_side>>>(ei);
    walpha_kernel<<<(F_IN * 32 + 255) / 256, 256, 0, s_side>>>(W1, a1s, a1d);
    alpha_direct_kernel<<<(N_NODES * 32 + 255) / 256, 256, 0, s_side>>>(x);
    cudaEventRecord(ev_side, s_side);

    // main stream: dense GEMM1 (cp.async double-buffered)
    dim3 g1((N_NODES + BM - 1) / BM, C1 / BN);
    gemm1_kernel<<<g1, 256, SMEM_GEMM>>>(x, W1);

    // join, then edge-dependent work on main stream
    cudaStreamWaitEvent(0, ev_side, 0);
    agg1_kernel<<<(N_NODES * 32 + 255) / 256, 256>>>(b1, W2, a2s, a2d);
    agg2_kernel<<<(N_NODES + 255) / 256, 256>>>(b2, out);
}